// round 11
// baseline (speedup 1.0000x reference)
#include <cuda_runtime.h>
#include <cuda_fp16.h>
#include <cstdint>

#define H 64
#define TILE 128
#define NT 128
#define RS 144                  // smem row stride (bytes): 9*16 -> conflict-free ldmatrix

// ---- smem layout (bytes) ----
#define OFF_AH   0               // h (fp16)        : 128 x 144 = 18432
#define OFF_W2H  18432           // W2 (fp16)       : 64 x 144 = 9216
#define OFF_MH   27648           // M  (fp16)       : 64 x 144
#define OFF_TBL  36864           // float4[64]: (b2, rsM, W3_0, W3_1)
#define OFF_W1A  37888           // float[64]
#define OFF_W1B  38144
#define OFF_B1   38400
#define OFF_B3   38656           // float[2]
#define SMEM_TOTAL 38912

__device__ __forceinline__ uint32_t smem_u32(const void* p){
    uint32_t a;
    asm("{ .reg .u64 t; cvta.to.shared.u64 t, %1; cvt.u32.u64 %0, t; }" : "=r"(a) : "l"(p));
    return a;
}
__device__ __forceinline__ void ldm_x4(uint32_t* r, uint32_t addr){
    asm volatile("ldmatrix.sync.aligned.m8n8.x4.shared.b16 {%0,%1,%2,%3}, [%4];"
        : "=r"(r[0]),"=r"(r[1]),"=r"(r[2]),"=r"(r[3]) : "r"(addr));
}
__device__ __forceinline__ void mma_f16(float* d, const uint32_t* a, const uint32_t* b){
    asm volatile("mma.sync.aligned.m16n8k16.row.col.f32.f16.f16.f32 "
        "{%0,%1,%2,%3}, {%4,%5,%6,%7}, {%8,%9}, {%0,%1,%2,%3};"
        : "+f"(d[0]),"+f"(d[1]),"+f"(d[2]),"+f"(d[3])
        : "r"(a[0]),"r"(a[1]),"r"(a[2]),"r"(a[3]), "r"(b[0]),"r"(b[1]));
}
__device__ __forceinline__ float elu(float x){ return x > 0.f ? x : (__expf(x) - 1.f); }

__device__ __forceinline__ uint32_t packh2(float a, float b){
    __half2 v = __floats2half2_rn(a, b);
    return *reinterpret_cast<uint32_t*>(&v);
}
// elementwise min(x, 0) on packed fp16
__device__ __forceinline__ uint32_t hmin0(uint32_t v){
    __half2 a = *reinterpret_cast<__half2*>(&v);
    __half2 z = __floats2half2_rn(0.f, 0.f);
    __half2 m = __hmin2(a, z);
    return *reinterpret_cast<uint32_t*>(&m);
}

__global__ __launch_bounds__(NT, 3)
void odefunc_mma(const float* __restrict__ zlp,
                 const float* __restrict__ W1, const float* __restrict__ b1,
                 const float* __restrict__ W2, const float* __restrict__ b2,
                 const float* __restrict__ W3, const float* __restrict__ b3,
                 float* __restrict__ out, int B, int ntiles)
{
    extern __shared__ char sm[];
    const uint32_t smb = smem_u32(sm);
    const int tid = threadIdx.x, w = tid >> 5, lane = tid & 31;

    float*  sW1a = (float*)(sm + OFF_W1A);
    float*  sW1b = (float*)(sm + OFF_W1B);
    float*  sB1  = (float*)(sm + OFF_B1);
    float*  sB3  = (float*)(sm + OFF_B3);
    float4* sTBL = (float4*)(sm + OFF_TBL);

    // ---------- per-CTA weight prep ----------
    for (int j = tid; j < H; j += NT){
        sW1a[j] = W1[2*j]; sW1b[j] = W1[2*j+1]; sB1[j] = b1[j];
    }
    if (tid < 2) sB3[tid] = b3[tid];

    for (int idx = tid; idx < H*H; idx += NT){
        int n = idx >> 6, j = idx & 63;            // n = output neuron, j = input
        float w2 = W2[idx];
        float c  = fmaf(W1[2*j], W3[n], W1[2*j+1] * W3[H + n]);   // C[j][n]
        uint32_t off = (uint32_t)(n*RS + 2*j);
        *(__half*)(sm + OFF_W2H + off) = __float2half_rn(w2);
        *(__half*)(sm + OFF_MH  + off) = __float2half_rn(w2 * c);
    }
    if (tid < H){
        float s = 0.f;
        #pragma unroll 8
        for (int j = 0; j < H; j++){
            float c = fmaf(W1[2*j], W3[tid], W1[2*j+1] * W3[H + tid]);
            s += W2[tid*H + j] * c;
        }
        sTBL[tid] = make_float4(b2[tid], s, W3[tid], W3[H + tid]);
    }
    __syncthreads();

    const float b30 = sB3[0], b31 = sB3[1];

    // ldmatrix lane address components
    const int aRow  = (lane & 7) + ((lane >> 3) & 1) * 8;     // A x4: rows within 16
    const int aColB = (lane >> 4) * 16;
    const int bRow4 = (lane & 7) + ((lane >> 4) & 1) * 8;     // B x4: n within ng-pair
    const int bCol4 = ((lane >> 3) & 1) * 16;

    const uint32_t aAH  = smb + OFF_AH + (uint32_t)((w*32 + aRow)*RS + aColB);
    const uint32_t bW2  = smb + OFF_W2H + (uint32_t)(bRow4*RS + bCol4);
    const uint32_t bM   = smb + OFF_MH  + (uint32_t)(bRow4*RS + bCol4);

    for (int tile = blockIdx.x; tile < ntiles; tile += gridDim.x){
        const int base = tile * TILE;
        const int s = base + tid;
        const bool ok = (s < B);
        float z0 = 0.f, z1 = 0.f;
        if (ok){ z0 = zlp[3*s]; z1 = zlp[3*s + 1]; }

        // ---- fill this thread's A row: h as fp16, 16B chunks ----
        {
            const uint32_t rbase = (uint32_t)tid * RS;
            #pragma unroll
            for (int jb = 0; jb < 8; jb++){
                uint4 vh;
                uint32_t* ph = (uint32_t*)&vh;
                #pragma unroll
                for (int q = 0; q < 4; q++){
                    int j = jb*8 + 2*q;
                    float a0 = fmaf(sW1a[j],   z0, fmaf(sW1b[j],   z1, sB1[j]));
                    float a1 = fmaf(sW1a[j+1], z0, fmaf(sW1b[j+1], z1, sB1[j+1]));
                    float h0 = ok ? elu(a0) : 0.f;
                    float h1 = ok ? elu(a1) : 0.f;
                    ph[q] = packh2(h0, h1);
                }
                *(uint4*)(sm + OFF_AH + rbase + jb*16) = vh;
            }
        }
        __syncwarp();

        // ---- warp-local GEMM: mt outer; B fragments loaded JIT from smem ----
        #pragma unroll
        for (int mt = 0; mt < 2; mt++){
            // A fragments for this m-tile, all kc (16 regs)
            uint32_t ah[4][4];
            #pragma unroll
            for (int kc = 0; kc < 4; kc++)
                ldm_x4(ah[kc], aAH + (uint32_t)(mt*16*RS + kc*32));

            float o0[2] = {0.f, 0.f}, o1[2] = {0.f, 0.f}, tr[2] = {0.f, 0.f};

            #pragma unroll
            for (int half = 0; half < 2; half++){
                float dv[4][4], dt[4][4];
                #pragma unroll
                for (int ng = 0; ng < 4; ng++)
                    #pragma unroll
                    for (int e = 0; e < 4; e++){ dv[ng][e] = 0.f; dt[ng][e] = 0.f; }

                #pragma unroll
                for (int kc = 0; kc < 4; kc++){
                    uint32_t roff0 = (uint32_t)((half*32     )*RS + kc*32);
                    uint32_t roff1 = (uint32_t)((half*32 + 16)*RS + kc*32);
                    uint32_t bv[8], bm[8];
                    ldm_x4(bv,     bW2 + roff0);
                    ldm_x4(bv + 4, bW2 + roff1);
                    ldm_x4(bm,     bM  + roff0);
                    ldm_x4(bm + 4, bM  + roff1);
                    uint32_t nh[4];
                    #pragma unroll
                    for (int e = 0; e < 4; e++) nh[e] = hmin0(ah[kc][e]);
                    #pragma unroll
                    for (int ng = 0; ng < 4; ng++){
                        mma_f16(dv[ng], ah[kc], bv + 2*ng);
                        mma_f16(dt[ng], nh,     bm + 2*ng);
                    }
                }

                // epilogue for this (mt, half)
                #pragma unroll
                for (int ng = 0; ng < 4; ng++){
                    int n0 = half*32 + ng*8 + 2*(lane & 3);
                    float4 t0 = sTBL[n0], t1 = sTBL[n0 + 1];
                    #pragma unroll
                    for (int rr = 0; rr < 2; rr++){
                        float v0 = dv[ng][2*rr],     tv0 = dt[ng][2*rr];
                        float v1 = dv[ng][2*rr + 1], tv1 = dt[ng][2*rr + 1];
                        float h2 = elu(v0 + t0.x);
                        o0[rr] = fmaf(t0.z, h2, o0[rr]);
                        o1[rr] = fmaf(t0.w, h2, o1[rr]);
                        tr[rr] = fmaf(1.f + fminf(h2, 0.f), tv0 + t0.y, tr[rr]);
                        float h3 = elu(v1 + t1.x);
                        o0[rr] = fmaf(t1.z, h3, o0[rr]);
                        o1[rr] = fmaf(t1.w, h3, o1[rr]);
                        tr[rr] = fmaf(1.f + fminf(h3, 0.f), tv1 + t1.y, tr[rr]);
                    }
                }
            }

            // ---- reduce across the 4 lanes of each row group, store (per mt) ----
            #pragma unroll
            for (int rr = 0; rr < 2; rr++){
                o0[rr] += __shfl_xor_sync(0xffffffffu, o0[rr], 1);
                o0[rr] += __shfl_xor_sync(0xffffffffu, o0[rr], 2);
                o1[rr] += __shfl_xor_sync(0xffffffffu, o1[rr], 1);
                o1[rr] += __shfl_xor_sync(0xffffffffu, o1[rr], 2);
                tr[rr] += __shfl_xor_sync(0xffffffffu, tr[rr], 1);
                tr[rr] += __shfl_xor_sync(0xffffffffu, tr[rr], 2);
            }
            if ((lane & 3) == 0){
                int g = lane >> 2;
                #pragma unroll
                for (int rr = 0; rr < 2; rr++){
                    int s2 = base + w*32 + mt*16 + g + rr*8;
                    if (s2 < B){
                        out[3*s2]     = o0[rr] + b30;
                        out[3*s2 + 1] = o1[rr] + b31;
                        out[3*s2 + 2] = -tr[rr];
                    }
                }
            }
        }
        __syncwarp();
    }
}

extern "C" void kernel_launch(void* const* d_in, const int* in_sizes, int n_in,
                              void* d_out, int out_size)
{
    // metadata order: t, z_and_logp, W1, b1, W2, b2, W3, b3
    const float* zlp = (const float*)d_in[1];
    const float* W1  = (const float*)d_in[2];
    const float* b1  = (const float*)d_in[3];
    const float* W2  = (const float*)d_in[4];
    const float* b2  = (const float*)d_in[5];
    const float* W3  = (const float*)d_in[6];
    const float* b3  = (const float*)d_in[7];
    float* out = (float*)d_out;
    int B = in_sizes[1] / 3;
    int ntiles = (B + TILE - 1) / TILE;

    cudaFuncSetAttribute(odefunc_mma, cudaFuncAttributeMaxDynamicSharedMemorySize, SMEM_TOTAL);
    int grid = 444;               // 3 CTAs x 148 SMs, persistent
    if (grid > ntiles) grid = ntiles;
    odefunc_mma<<<grid, NT, SMEM_TOTAL>>>(zlp, W1, b1, W2, b2, W3, b3, out, B, ntiles);
}